// round 2
// baseline (speedup 1.0000x reference)
#include <cuda_runtime.h>

#define NN 50000
#define NE 800000
#define DH 128
#define DE 16

// Scratch (static __device__ to respect allocation guards)
__device__ float g_deg[NN];
__device__ float g_dis[NN];
__device__ float g_hxs[NN * DH];
__device__ float g_agg1[NN * DH];
__device__ float g_agg2[NN * DH];
__device__ float g_h[NN * DH];

__device__ __forceinline__ void fma4(float4& acc, float a, const float4 w) {
    acc.x = fmaf(a, w.x, acc.x);
    acc.y = fmaf(a, w.y, acc.y);
    acc.z = fmaf(a, w.z, acc.z);
    acc.w = fmaf(a, w.w, acc.w);
}

__device__ __forceinline__ float get_comp(const float4 v, int i) {
    return i == 0 ? v.x : (i == 1 ? v.y : (i == 2 ? v.z : v.w));
}

// 128-bit vector reduction (Hopper+/Blackwell): 1 instr instead of 4 scalar REDs
__device__ __forceinline__ void red4(float* p, float4 v) {
    asm volatile("red.global.add.v4.f32 [%0], {%1,%2,%3,%4};"
                 :: "l"(p), "f"(v.x), "f"(v.y), "f"(v.z), "f"(v.w)
                 : "memory");
}

// ---------------------------------------------------------------------------
// degree / normalization
// ---------------------------------------------------------------------------
__global__ void deg_kernel(const int* __restrict__ col) {
    for (int i = blockIdx.x * blockDim.x + threadIdx.x; i < NE;
         i += gridDim.x * blockDim.x)
        atomicAdd(&g_deg[col[i]], 1.0f);
}

__global__ void dis_kernel() {
    int i = blockIdx.x * blockDim.x + threadIdx.x;
    if (i < NN) {
        float d = g_deg[i];
        g_dis[i] = (d > 0.0f) ? rsqrtf(d) : 0.0f;
    }
}

// ---------------------------------------------------------------------------
// GEMM: hxs[i,:] = (in[i,:] @ W) * dis[i]
// block = 256 threads (8 warps), each warp computes 4 rows; W cached in smem.
// ---------------------------------------------------------------------------
#define SMEM_GEMM ((DH * DH + 8 * 4 * DH) * 4)  // 81920 bytes

__global__ void __launch_bounds__(256) gemm_hxs_kernel(
    const float* __restrict__ in, const float* __restrict__ W)
{
    extern __shared__ float sm[];
    float* Ws = sm;                              // 128x128
    int warp = threadIdx.x >> 5, lane = threadIdx.x & 31;
    float* xs = sm + DH * DH + warp * 4 * DH;    // 4 rows per warp

    for (int i = threadIdx.x; i < (DH * DH) / 4; i += blockDim.x)
        ((float4*)Ws)[i] = ((const float4*)W)[i];

    int rowBase = blockIdx.x * 32 + warp * 4;
#pragma unroll
    for (int r = 0; r < 4; ++r) {
        int row = rowBase + r;
        float4 v = make_float4(0.f, 0.f, 0.f, 0.f);
        if (row < NN) v = ((const float4*)(in + (size_t)row * DH))[lane];
        ((float4*)(xs + r * DH))[lane] = v;
    }
    __syncthreads();

    float4 acc[4];
#pragma unroll
    for (int r = 0; r < 4; ++r) acc[r] = make_float4(0.f, 0.f, 0.f, 0.f);

#pragma unroll 4
    for (int k4 = 0; k4 < 32; ++k4) {
        float4 x0 = ((const float4*)(xs + 0 * DH))[k4];
        float4 x1 = ((const float4*)(xs + 1 * DH))[k4];
        float4 x2 = ((const float4*)(xs + 2 * DH))[k4];
        float4 x3 = ((const float4*)(xs + 3 * DH))[k4];
#pragma unroll
        for (int kk = 0; kk < 4; ++kk) {
            float4 w4 = ((const float4*)(Ws + (k4 * 4 + kk) * DH))[lane];
            fma4(acc[0], get_comp(x0, kk), w4);
            fma4(acc[1], get_comp(x1, kk), w4);
            fma4(acc[2], get_comp(x2, kk), w4);
            fma4(acc[3], get_comp(x3, kk), w4);
        }
    }

#pragma unroll
    for (int r = 0; r < 4; ++r) {
        int row = rowBase + r;
        if (row < NN) {
            float s = g_dis[row];
            float4 o = acc[r];
            o.x *= s; o.y *= s; o.z *= s; o.w *= s;
            ((float4*)(g_hxs + (size_t)row * DH))[lane] = o;
        }
    }
}

// ---------------------------------------------------------------------------
// Edge kernel: per edge e:
//   hid = relu(edge_attr[e] @ W1 + b1)           (16 -> 128)
//   agg2[col[e]] += hid        (RED.v4)
//   agg1[col[e]] += hxs[row[e]] (gather + RED.v4)
// One warp per edge; lane j owns features 4j..4j+3.
// ---------------------------------------------------------------------------
__global__ void __launch_bounds__(256) edge_kernel(
    const float* __restrict__ edge_attr,
    const int* __restrict__ row_idx,
    const int* __restrict__ col_idx,
    const float* __restrict__ W1,
    const float* __restrict__ b1)
{
    __shared__ float Ws[DE * DH];
    __shared__ float bs[DH];
    for (int i = threadIdx.x; i < DE * DH; i += blockDim.x) Ws[i] = W1[i];
    for (int i = threadIdx.x; i < DH; i += blockDim.x) bs[i] = b1[i];
    __syncthreads();

    int lane = threadIdx.x & 31;
    int gw = (blockIdx.x * blockDim.x + threadIdx.x) >> 5;
    int nw = (gridDim.x * blockDim.x) >> 5;
    int j4 = lane * 4;

    for (int e = gw; e < NE; e += nw) {
        int r = __ldg(row_idx + e);
        int c = __ldg(col_idx + e);
        float av = (lane < DE) ? __ldg(edge_attr + (size_t)e * DE + lane) : 0.0f;

        float4 acc = *(const float4*)(bs + j4);
#pragma unroll
        for (int k = 0; k < DE; ++k) {
            float a = __shfl_sync(0xffffffffu, av, k);
            float4 w4 = *(const float4*)(Ws + k * DH + j4);
            fma4(acc, a, w4);
        }
        acc.x = fmaxf(acc.x, 0.f); acc.y = fmaxf(acc.y, 0.f);
        acc.z = fmaxf(acc.z, 0.f); acc.w = fmaxf(acc.w, 0.f);

        red4(g_agg2 + (size_t)c * DH + j4, acc);

        float4 hv = *(const float4*)(g_hxs + (size_t)r * DH + j4);
        red4(g_agg1 + (size_t)c * DH + j4, hv);
    }
}

// ---------------------------------------------------------------------------
// Node kernel: out = dis[i]*agg1[i,:] + agg2[i,:] @ W2 + deg[i]*b2 + bias
//              then LayerNorm + ReLU -> dst
// ---------------------------------------------------------------------------
__global__ void __launch_bounds__(256) node_kernel(
    const float* __restrict__ W2,
    const float* __restrict__ b2,
    const float* __restrict__ bias,
    const float* __restrict__ lnw,
    const float* __restrict__ lnb,
    float* __restrict__ dst)
{
    extern __shared__ float sm[];
    float* Ws = sm;
    int warp = threadIdx.x >> 5, lane = threadIdx.x & 31;
    float* xs = sm + DH * DH + warp * 4 * DH;

    for (int i = threadIdx.x; i < (DH * DH) / 4; i += blockDim.x)
        ((float4*)Ws)[i] = ((const float4*)W2)[i];

    int rowBase = blockIdx.x * 32 + warp * 4;
#pragma unroll
    for (int r = 0; r < 4; ++r) {
        int row = rowBase + r;
        float4 v = make_float4(0.f, 0.f, 0.f, 0.f);
        if (row < NN) v = ((const float4*)(g_agg2 + (size_t)row * DH))[lane];
        ((float4*)(xs + r * DH))[lane] = v;
    }
    __syncthreads();

    float4 acc[4];
#pragma unroll
    for (int r = 0; r < 4; ++r) acc[r] = make_float4(0.f, 0.f, 0.f, 0.f);

#pragma unroll 4
    for (int k4 = 0; k4 < 32; ++k4) {
        float4 x0 = ((const float4*)(xs + 0 * DH))[k4];
        float4 x1 = ((const float4*)(xs + 1 * DH))[k4];
        float4 x2 = ((const float4*)(xs + 2 * DH))[k4];
        float4 x3 = ((const float4*)(xs + 3 * DH))[k4];
#pragma unroll
        for (int kk = 0; kk < 4; ++kk) {
            float4 w4 = ((const float4*)(Ws + (k4 * 4 + kk) * DH))[lane];
            fma4(acc[0], get_comp(x0, kk), w4);
            fma4(acc[1], get_comp(x1, kk), w4);
            fma4(acc[2], get_comp(x2, kk), w4);
            fma4(acc[3], get_comp(x3, kk), w4);
        }
    }

    float4 b2v = ((const float4*)b2)[lane];
    float4 biv = ((const float4*)bias)[lane];
    float4 lwv = ((const float4*)lnw)[lane];
    float4 lbv = ((const float4*)lnb)[lane];

#pragma unroll
    for (int r = 0; r < 4; ++r) {
        int row = rowBase + r;
        float4 v = acc[r];
        if (row < NN) {
            float4 a1 = ((const float4*)(g_agg1 + (size_t)row * DH))[lane];
            float dis = g_dis[row];
            float dg = g_deg[row];
            v.x += dis * a1.x + dg * b2v.x + biv.x;
            v.y += dis * a1.y + dg * b2v.y + biv.y;
            v.z += dis * a1.z + dg * b2v.z + biv.z;
            v.w += dis * a1.w + dg * b2v.w + biv.w;
        }
        // LayerNorm across the 128 features held by this warp (4/lane)
        float s = v.x + v.y + v.z + v.w;
#pragma unroll
        for (int o = 16; o > 0; o >>= 1) s += __shfl_xor_sync(0xffffffffu, s, o);
        float mu = s * (1.0f / 128.0f);
        float dx = v.x - mu, dy = v.y - mu, dz = v.z - mu, dw = v.w - mu;
        float q = dx * dx + dy * dy + dz * dz + dw * dw;
#pragma unroll
        for (int o = 16; o > 0; o >>= 1) q += __shfl_xor_sync(0xffffffffu, q, o);
        float rstd = rsqrtf(q * (1.0f / 128.0f) + 1e-5f);

        float4 o4;
        o4.x = fmaxf(dx * rstd * lwv.x + lbv.x, 0.f);
        o4.y = fmaxf(dy * rstd * lwv.y + lbv.y, 0.f);
        o4.z = fmaxf(dz * rstd * lwv.z + lbv.z, 0.f);
        o4.w = fmaxf(dw * rstd * lwv.w + lbv.w, 0.f);
        if (row < NN)
            ((float4*)(dst + (size_t)row * DH))[lane] = o4;
    }
}

// ---------------------------------------------------------------------------
extern "C" void kernel_launch(void* const* d_in, const int* in_sizes, int n_in,
                              void* d_out, int out_size)
{
    const float* x   = (const float*)d_in[0];
    const float* ea  = (const float*)d_in[1];
    const float* lw  = (const float*)d_in[2];   // [3,128,128]
    const float* ew1 = (const float*)d_in[3];   // [3,16,128]
    const float* eb1 = (const float*)d_in[4];   // [3,128]
    const float* ew2 = (const float*)d_in[5];   // [3,128,128]
    const float* eb2 = (const float*)d_in[6];   // [3,128]
    const float* bi  = (const float*)d_in[7];   // [3,128]
    const float* lnw = (const float*)d_in[8];   // [3,128]
    const float* lnb = (const float*)d_in[9];   // [3,128]
    const int*   eidx = (const int*)d_in[10];   // [2,E]
    const int* rowi = eidx;
    const int* coli = eidx + NE;

    void *p_deg, *p_agg1, *p_agg2, *p_h;
    cudaGetSymbolAddress(&p_deg, g_deg);
    cudaGetSymbolAddress(&p_agg1, g_agg1);
    cudaGetSymbolAddress(&p_agg2, g_agg2);
    cudaGetSymbolAddress(&p_h, g_h);

    cudaFuncSetAttribute(gemm_hxs_kernel,
                         cudaFuncAttributeMaxDynamicSharedMemorySize, SMEM_GEMM);
    cudaFuncSetAttribute(node_kernel,
                         cudaFuncAttributeMaxDynamicSharedMemorySize, SMEM_GEMM);

    const int GRID_GEMM = (NN + 31) / 32;  // 1563

    cudaMemsetAsync(p_deg, 0, NN * sizeof(float), 0);
    deg_kernel<<<1024, 256>>>(coli);
    dis_kernel<<<(NN + 255) / 256, 256>>>();

    for (int l = 0; l < 3; ++l) {
        cudaMemsetAsync(p_agg1, 0, (size_t)NN * DH * sizeof(float), 0);
        cudaMemsetAsync(p_agg2, 0, (size_t)NN * DH * sizeof(float), 0);

        const float* hin = (l == 0) ? x : (const float*)p_h;
        gemm_hxs_kernel<<<GRID_GEMM, 256, SMEM_GEMM>>>(hin, lw + (size_t)l * DH * DH);

        edge_kernel<<<2048, 256>>>(ea, rowi, coli,
                                   ew1 + (size_t)l * DE * DH, eb1 + (size_t)l * DH);

        float* dst = (l == 2) ? (float*)d_out : (float*)p_h;
        node_kernel<<<GRID_GEMM, 256, SMEM_GEMM>>>(
            ew2 + (size_t)l * DH * DH, eb2 + (size_t)l * DH, bi + (size_t)l * DH,
            lnw + (size_t)l * DH, lnb + (size_t)l * DH, dst);
    }
}

// round 3
// speedup vs baseline: 1.1283x; 1.1283x over previous
#include <cuda_runtime.h>

#define NN 50000
#define NE 800000
#define DH 128
#define DE 16

// Scratch (static __device__ to respect allocation guards)
__device__ float g_deg[NN];
__device__ float g_dis[NN];
__device__ float g_hxs[NN * DH];
__device__ float g_agg1[NN * DH];
__device__ float g_agg2[NN * DH];
__device__ float g_h[NN * DH];

__device__ __forceinline__ void fma4(float4& acc, float a, const float4 w) {
    acc.x = fmaf(a, w.x, acc.x);
    acc.y = fmaf(a, w.y, acc.y);
    acc.z = fmaf(a, w.z, acc.z);
    acc.w = fmaf(a, w.w, acc.w);
}

__device__ __forceinline__ float get_comp(const float4 v, int i) {
    return i == 0 ? v.x : (i == 1 ? v.y : (i == 2 ? v.z : v.w));
}

// 128-bit vector reduction: 1 instruction instead of 4 scalar REDs
__device__ __forceinline__ void red4(float* p, float4 v) {
    asm volatile("red.global.add.v4.f32 [%0], {%1,%2,%3,%4};"
                 :: "l"(p), "f"(v.x), "f"(v.y), "f"(v.z), "f"(v.w)
                 : "memory");
}

// ---------------------------------------------------------------------------
// degree / normalization
// ---------------------------------------------------------------------------
__global__ void deg_kernel(const int* __restrict__ col) {
    for (int i = blockIdx.x * blockDim.x + threadIdx.x; i < NE;
         i += gridDim.x * blockDim.x)
        atomicAdd(&g_deg[col[i]], 1.0f);
}

__global__ void dis_kernel() {
    int i = blockIdx.x * blockDim.x + threadIdx.x;
    if (i < NN) {
        float d = g_deg[i];
        g_dis[i] = (d > 0.0f) ? rsqrtf(d) : 0.0f;
    }
}

// ---------------------------------------------------------------------------
// GEMM: hxs[i,:] = (in[i,:] @ W) * dis[i]
// ---------------------------------------------------------------------------
#define SMEM_GEMM ((DH * DH + 8 * 4 * DH) * 4)  // 81920 bytes

__global__ void __launch_bounds__(256) gemm_hxs_kernel(
    const float* __restrict__ in, const float* __restrict__ W)
{
    extern __shared__ float sm[];
    float* Ws = sm;                              // 128x128
    int warp = threadIdx.x >> 5, lane = threadIdx.x & 31;
    float* xs = sm + DH * DH + warp * 4 * DH;    // 4 rows per warp

    for (int i = threadIdx.x; i < (DH * DH) / 4; i += blockDim.x)
        ((float4*)Ws)[i] = ((const float4*)W)[i];

    int rowBase = blockIdx.x * 32 + warp * 4;
#pragma unroll
    for (int r = 0; r < 4; ++r) {
        int row = rowBase + r;
        float4 v = make_float4(0.f, 0.f, 0.f, 0.f);
        if (row < NN) v = ((const float4*)(in + (size_t)row * DH))[lane];
        ((float4*)(xs + r * DH))[lane] = v;
    }
    __syncthreads();

    float4 acc[4];
#pragma unroll
    for (int r = 0; r < 4; ++r) acc[r] = make_float4(0.f, 0.f, 0.f, 0.f);

#pragma unroll 4
    for (int k4 = 0; k4 < 32; ++k4) {
        float4 x0 = ((const float4*)(xs + 0 * DH))[k4];
        float4 x1 = ((const float4*)(xs + 1 * DH))[k4];
        float4 x2 = ((const float4*)(xs + 2 * DH))[k4];
        float4 x3 = ((const float4*)(xs + 3 * DH))[k4];
#pragma unroll
        for (int kk = 0; kk < 4; ++kk) {
            float4 w4 = ((const float4*)(Ws + (k4 * 4 + kk) * DH))[lane];
            fma4(acc[0], get_comp(x0, kk), w4);
            fma4(acc[1], get_comp(x1, kk), w4);
            fma4(acc[2], get_comp(x2, kk), w4);
            fma4(acc[3], get_comp(x3, kk), w4);
        }
    }

#pragma unroll
    for (int r = 0; r < 4; ++r) {
        int row = rowBase + r;
        if (row < NN) {
            float s = g_dis[row];
            float4 o = acc[r];
            o.x *= s; o.y *= s; o.z *= s; o.w *= s;
            ((float4*)(g_hxs + (size_t)row * DH))[lane] = o;
        }
    }
}

// ---------------------------------------------------------------------------
// Edge kernel: per edge e (one warp per edge, lane j owns features 4j..4j+3):
//   hid = relu(edge_attr[e] @ W1 + b1)    (16 -> 128, W1 in REGISTERS)
//   agg2[col[e]] += hid                   (RED.v4)
//   agg1[col[e]] += hxs[row[e]]           (gather + RED.v4)
// W1/b1 are register-resident per lane: no smem in the hot loop at all.
// ---------------------------------------------------------------------------
__global__ void __launch_bounds__(128) edge_kernel(
    const float* __restrict__ edge_attr,
    const int* __restrict__ row_idx,
    const int* __restrict__ col_idx,
    const float* __restrict__ W1,
    const float* __restrict__ b1)
{
    int lane = threadIdx.x & 31;
    int j4 = lane * 4;

    // Per-lane register slice of W1 (16 x float4) and bias (float4).
    // Lane j reads W1[k*128 + 4j .. +3] -> coalesced LDG.128 across the warp.
    float4 w[DE];
#pragma unroll
    for (int k = 0; k < DE; ++k)
        w[k] = *(const float4*)(W1 + k * DH + j4);
    const float4 bv = *(const float4*)(b1 + j4);

    int gw = (blockIdx.x * blockDim.x + threadIdx.x) >> 5;
    int nw = (gridDim.x * blockDim.x) >> 5;

    for (int e = gw; e < NE; e += nw) {
        int r = __ldg(row_idx + e);
        int c = __ldg(col_idx + e);
        // Issue the gather early so its L2 latency hides under the MLP.
        float4 hv = *(const float4*)(g_hxs + (size_t)r * DH + j4);
        float av = (lane < DE) ? __ldg(edge_attr + (size_t)e * DE + lane) : 0.0f;

        float4 acc = bv;
#pragma unroll
        for (int k = 0; k < DE; ++k) {
            float a = __shfl_sync(0xffffffffu, av, k);
            fma4(acc, a, w[k]);
        }
        acc.x = fmaxf(acc.x, 0.f); acc.y = fmaxf(acc.y, 0.f);
        acc.z = fmaxf(acc.z, 0.f); acc.w = fmaxf(acc.w, 0.f);

        float* base = g_agg2 + (size_t)c * DH + j4;
        red4(base, acc);
        red4(base + (g_agg1 - g_agg2), hv);
    }
}

// ---------------------------------------------------------------------------
// Node kernel: out = dis[i]*agg1[i,:] + agg2[i,:] @ W2 + deg[i]*b2 + bias
//              then LayerNorm + ReLU -> dst
// ---------------------------------------------------------------------------
__global__ void __launch_bounds__(256) node_kernel(
    const float* __restrict__ W2,
    const float* __restrict__ b2,
    const float* __restrict__ bias,
    const float* __restrict__ lnw,
    const float* __restrict__ lnb,
    float* __restrict__ dst)
{
    extern __shared__ float sm[];
    float* Ws = sm;
    int warp = threadIdx.x >> 5, lane = threadIdx.x & 31;
    float* xs = sm + DH * DH + warp * 4 * DH;

    for (int i = threadIdx.x; i < (DH * DH) / 4; i += blockDim.x)
        ((float4*)Ws)[i] = ((const float4*)W2)[i];

    int rowBase = blockIdx.x * 32 + warp * 4;
#pragma unroll
    for (int r = 0; r < 4; ++r) {
        int row = rowBase + r;
        float4 v = make_float4(0.f, 0.f, 0.f, 0.f);
        if (row < NN) v = ((const float4*)(g_agg2 + (size_t)row * DH))[lane];
        ((float4*)(xs + r * DH))[lane] = v;
    }
    __syncthreads();

    float4 acc[4];
#pragma unroll
    for (int r = 0; r < 4; ++r) acc[r] = make_float4(0.f, 0.f, 0.f, 0.f);

#pragma unroll 4
    for (int k4 = 0; k4 < 32; ++k4) {
        float4 x0 = ((const float4*)(xs + 0 * DH))[k4];
        float4 x1 = ((const float4*)(xs + 1 * DH))[k4];
        float4 x2 = ((const float4*)(xs + 2 * DH))[k4];
        float4 x3 = ((const float4*)(xs + 3 * DH))[k4];
#pragma unroll
        for (int kk = 0; kk < 4; ++kk) {
            float4 w4 = ((const float4*)(Ws + (k4 * 4 + kk) * DH))[lane];
            fma4(acc[0], get_comp(x0, kk), w4);
            fma4(acc[1], get_comp(x1, kk), w4);
            fma4(acc[2], get_comp(x2, kk), w4);
            fma4(acc[3], get_comp(x3, kk), w4);
        }
    }

    float4 b2v = ((const float4*)b2)[lane];
    float4 biv = ((const float4*)bias)[lane];
    float4 lwv = ((const float4*)lnw)[lane];
    float4 lbv = ((const float4*)lnb)[lane];

#pragma unroll
    for (int r = 0; r < 4; ++r) {
        int row = rowBase + r;
        float4 v = acc[r];
        if (row < NN) {
            float4 a1 = ((const float4*)(g_agg1 + (size_t)row * DH))[lane];
            float dis = g_dis[row];
            float dg = g_deg[row];
            v.x += dis * a1.x + dg * b2v.x + biv.x;
            v.y += dis * a1.y + dg * b2v.y + biv.y;
            v.z += dis * a1.z + dg * b2v.z + biv.z;
            v.w += dis * a1.w + dg * b2v.w + biv.w;
        }
        // LayerNorm across 128 features held by this warp (4/lane)
        float s = v.x + v.y + v.z + v.w;
#pragma unroll
        for (int o = 16; o > 0; o >>= 1) s += __shfl_xor_sync(0xffffffffu, s, o);
        float mu = s * (1.0f / 128.0f);
        float dx = v.x - mu, dy = v.y - mu, dz = v.z - mu, dw = v.w - mu;
        float q = dx * dx + dy * dy + dz * dz + dw * dw;
#pragma unroll
        for (int o = 16; o > 0; o >>= 1) q += __shfl_xor_sync(0xffffffffu, q, o);
        float rstd = rsqrtf(q * (1.0f / 128.0f) + 1e-5f);

        float4 o4;
        o4.x = fmaxf(dx * rstd * lwv.x + lbv.x, 0.f);
        o4.y = fmaxf(dy * rstd * lwv.y + lbv.y, 0.f);
        o4.z = fmaxf(dz * rstd * lwv.z + lbv.z, 0.f);
        o4.w = fmaxf(dw * rstd * lwv.w + lbv.w, 0.f);
        if (row < NN)
            ((float4*)(dst + (size_t)row * DH))[lane] = o4;
    }
}

// ---------------------------------------------------------------------------
extern "C" void kernel_launch(void* const* d_in, const int* in_sizes, int n_in,
                              void* d_out, int out_size)
{
    const float* x   = (const float*)d_in[0];
    const float* ea  = (const float*)d_in[1];
    const float* lw  = (const float*)d_in[2];   // [3,128,128]
    const float* ew1 = (const float*)d_in[3];   // [3,16,128]
    const float* eb1 = (const float*)d_in[4];   // [3,128]
    const float* ew2 = (const float*)d_in[5];   // [3,128,128]
    const float* eb2 = (const float*)d_in[6];   // [3,128]
    const float* bi  = (const float*)d_in[7];   // [3,128]
    const float* lnw = (const float*)d_in[8];   // [3,128]
    const float* lnb = (const float*)d_in[9];   // [3,128]
    const int*   eidx = (const int*)d_in[10];   // [2,E]
    const int* rowi = eidx;
    const int* coli = eidx + NE;

    void *p_deg, *p_agg1, *p_agg2, *p_h;
    cudaGetSymbolAddress(&p_deg, g_deg);
    cudaGetSymbolAddress(&p_agg1, g_agg1);
    cudaGetSymbolAddress(&p_agg2, g_agg2);
    cudaGetSymbolAddress(&p_h, g_h);

    cudaFuncSetAttribute(gemm_hxs_kernel,
                         cudaFuncAttributeMaxDynamicSharedMemorySize, SMEM_GEMM);
    cudaFuncSetAttribute(node_kernel,
                         cudaFuncAttributeMaxDynamicSharedMemorySize, SMEM_GEMM);

    const int GRID_GEMM = (NN + 31) / 32;  // 1563

    cudaMemsetAsync(p_deg, 0, NN * sizeof(float), 0);
    deg_kernel<<<1024, 256>>>(coli);
    dis_kernel<<<(NN + 255) / 256, 256>>>();

    for (int l = 0; l < 3; ++l) {
        cudaMemsetAsync(p_agg1, 0, (size_t)NN * DH * sizeof(float), 0);
        cudaMemsetAsync(p_agg2, 0, (size_t)NN * DH * sizeof(float), 0);

        const float* hin = (l == 0) ? x : (const float*)p_h;
        gemm_hxs_kernel<<<GRID_GEMM, 256, SMEM_GEMM>>>(hin, lw + (size_t)l * DH * DH);

        edge_kernel<<<4096, 128>>>(ea, rowi, coli,
                                   ew1 + (size_t)l * DE * DH, eb1 + (size_t)l * DH);

        float* dst = (l == 2) ? (float*)d_out : (float*)p_h;
        node_kernel<<<GRID_GEMM, 256, SMEM_GEMM>>>(
            ew2 + (size_t)l * DH * DH, eb2 + (size_t)l * DH, bi + (size_t)l * DH,
            lnw + (size_t)l * DH, lnb + (size_t)l * DH, dst);
    }
}